// round 2
// baseline (speedup 1.0000x reference)
#include <cuda_runtime.h>
#include <cstdint>

#define NNODES 50000
#define NEDGES 800000
#define INF_   512
#define HIDDEN 64
#define HEADS  4
#define NCLS   40
#define F1     (HEADS*HIDDEN)   // 256

// ---------------- scratch (device globals; no allocation allowed) ----------------
__device__ float    g_h1 [NNODES*F1];      // x @ W1
__device__ float    g_out1[NNODES*F1];     // layer1 aggregation -> then elu'd h
__device__ float    g_as1[NNODES*HEADS];
__device__ float    g_ad1[NNODES*HEADS];
__device__ unsigned g_m1 [NNODES*HEADS];
__device__ float    g_den1[NNODES*HEADS];
__device__ float    g_h2 [NNODES*HIDDEN];  // h @ W2
__device__ float    g_out2[NNODES*HIDDEN];
__device__ float    g_as2[NNODES];
__device__ float    g_ad2[NNODES];
__device__ unsigned g_m2 [NNODES];
__device__ float    g_den2[NNODES];
__device__ float    g_emb[NNODES*HIDDEN];

// ---------------- helpers ----------------
__device__ __forceinline__ unsigned fenc(float f) {
    unsigned u = __float_as_uint(f);
    return (u & 0x80000000u) ? ~u : (u | 0x80000000u);
}
__device__ __forceinline__ float fdec(unsigned u) {
    return (u & 0x80000000u) ? __uint_as_float(u & 0x7FFFFFFFu) : __uint_as_float(~u);
}
__device__ __forceinline__ void red_add_v4(float* addr, float4 v) {
    asm volatile("red.global.add.v4.f32 [%0], {%1,%2,%3,%4};"
                 :: "l"(addr), "f"(v.x), "f"(v.y), "f"(v.z), "f"(v.w) : "memory");
}
__device__ __forceinline__ float lrelu(float v) { return v > 0.f ? v : 0.2f * v; }

// ---------------- SIMT register-tiled fp32 GEMM: C[M,Nn] = A[M,K] @ B[K,Nn] ----------------
template<int BM, int BN, int BK, int TM, int TN>
__global__ __launch_bounds__((BM/TM)*(BN/TN))
void sgemm(int M, int Nn, int K,
           const float* __restrict__ A, const float* __restrict__ B, float* __restrict__ C) {
    constexpr int THREADS = (BM/TM)*(BN/TN);
    __shared__ float As[BK][BM];
    __shared__ float Bs[BK][BN];
    const int t  = threadIdx.x;
    const int tx = t % (BN/TN);
    const int ty = t / (BN/TN);
    const int m0 = blockIdx.y * BM;
    const int n0 = blockIdx.x * BN;

    float acc[TM][TN];
#pragma unroll
    for (int i = 0; i < TM; i++)
#pragma unroll
        for (int j = 0; j < TN; j++) acc[i][j] = 0.f;

    constexpr int A_LD4 = BM * BK / 4;
    constexpr int B_LD4 = BK * BN / 4;

    for (int k0 = 0; k0 < K; k0 += BK) {
#pragma unroll
        for (int i = t; i < A_LD4; i += THREADS) {
            int row = i / (BK/4), kq = i % (BK/4);
            float4 v = make_float4(0.f, 0.f, 0.f, 0.f);
            int gm = m0 + row;
            if (gm < M) v = *(const float4*)&A[(size_t)gm * K + k0 + kq*4];
            As[kq*4+0][row] = v.x; As[kq*4+1][row] = v.y;
            As[kq*4+2][row] = v.z; As[kq*4+3][row] = v.w;
        }
#pragma unroll
        for (int i = t; i < B_LD4; i += THREADS) {
            int row = i / (BN/4), q = i % (BN/4);
            *(float4*)&Bs[row][q*4] = *(const float4*)&B[(size_t)(k0+row) * Nn + n0 + q*4];
        }
        __syncthreads();
#pragma unroll
        for (int k = 0; k < BK; k++) {
            float ar[TM], br[TN];
#pragma unroll
            for (int i = 0; i < TM; i += 4) *(float4*)&ar[i] = *(float4*)&As[k][ty*TM + i];
#pragma unroll
            for (int j = 0; j < TN; j += 4) *(float4*)&br[j] = *(float4*)&Bs[k][tx*TN + j];
#pragma unroll
            for (int i = 0; i < TM; i++)
#pragma unroll
                for (int j = 0; j < TN; j++) acc[i][j] += ar[i] * br[j];
        }
        __syncthreads();
    }
#pragma unroll
    for (int i = 0; i < TM; i++) {
        int gm = m0 + ty*TM + i;
        if (gm < M) {
#pragma unroll
            for (int j = 0; j < TN; j += 4) {
                float4 v = make_float4(acc[i][j], acc[i][j+1], acc[i][j+2], acc[i][j+3]);
                *(float4*)&C[(size_t)gm * Nn + n0 + tx*TN + j] = v;
            }
        }
    }
}

// ---------------- attention scores ----------------
__global__ __launch_bounds__(256) void attn_scores1(const float* __restrict__ att_src,
                                                    const float* __restrict__ att_dst) {
    int idx = blockIdx.x * blockDim.x + threadIdx.x;   // n*HEADS + h
    if (idx >= NNODES * HEADS) return;
    int n = idx >> 2, h = idx & 3;
    const float4* hp = (const float4*)&g_h1[(size_t)n * F1 + h * HIDDEN];
    const float4* sp = (const float4*)&att_src[h * HIDDEN];
    const float4* dp = (const float4*)&att_dst[h * HIDDEN];
    float sa = 0.f, da = 0.f;
#pragma unroll
    for (int i = 0; i < HIDDEN/4; i++) {
        float4 v = hp[i], s = sp[i], d = dp[i];
        sa += v.x*s.x + v.y*s.y + v.z*s.z + v.w*s.w;
        da += v.x*d.x + v.y*d.y + v.z*d.z + v.w*d.w;
    }
    g_as1[idx] = sa; g_ad1[idx] = da;
}

__global__ __launch_bounds__(256) void attn_scores2(const float* __restrict__ att_src,
                                                    const float* __restrict__ att_dst) {
    int n = blockIdx.x * blockDim.x + threadIdx.x;
    if (n >= NNODES) return;
    const float4* hp = (const float4*)&g_h2[(size_t)n * HIDDEN];
    const float4* sp = (const float4*)att_src;
    const float4* dp = (const float4*)att_dst;
    float sa = 0.f, da = 0.f;
#pragma unroll
    for (int i = 0; i < HIDDEN/4; i++) {
        float4 v = hp[i], s = sp[i], d = dp[i];
        sa += v.x*s.x + v.y*s.y + v.z*s.z + v.w*s.w;
        da += v.x*d.x + v.y*d.y + v.z*d.z + v.w*d.w;
    }
    g_as2[n] = sa; g_ad2[n] = da;
}

// ---------------- edge pass 1: segment max ----------------
__global__ __launch_bounds__(256) void edge_max1(const int* __restrict__ ei) {
    int idx = blockIdx.x * blockDim.x + threadIdx.x;   // e*HEADS + h
    if (idx >= NEDGES * HEADS) return;
    int e = idx >> 2, h = idx & 3;
    int src = ei[e], dst = ei[NEDGES + e];
    float v = lrelu(g_as1[src*HEADS + h] + g_ad1[dst*HEADS + h]);
    atomicMax(&g_m1[dst*HEADS + h], fenc(v));
}

__global__ __launch_bounds__(256) void edge_max2(const int* __restrict__ ei) {
    int e = blockIdx.x * blockDim.x + threadIdx.x;
    if (e >= NEDGES) return;
    int src = ei[e], dst = ei[NEDGES + e];
    float v = lrelu(g_as2[src] + g_ad2[dst]);
    atomicMax(&g_m2[dst], fenc(v));
}

// ---------------- edge pass 2: weighted scatter ----------------
__global__ __launch_bounds__(256) void edge_scatter1(const int* __restrict__ ei) {
    int warp = (blockIdx.x * blockDim.x + threadIdx.x) >> 5;
    int lane = threadIdx.x & 31;
    if (warp >= NEDGES) return;
    int src = ei[warp], dst = ei[NEDGES + warp];
    float w = 0.f;
    if (lane < HEADS) {
        float v = lrelu(g_as1[src*HEADS + lane] + g_ad1[dst*HEADS + lane]);
        w = expf(v - fdec(g_m1[dst*HEADS + lane]));
        atomicAdd(&g_den1[dst*HEADS + lane], w);
    }
#pragma unroll
    for (int j = 0; j < 2; j++) {
        int f = j*32 + lane;          // float4 index, 0..63
        int h = f >> 4;               // 16 float4s per head
        float wh = __shfl_sync(0xffffffffu, w, h);
        float4 v = *(const float4*)&g_h1[(size_t)src * F1 + f*4];
        red_add_v4(&g_out1[(size_t)dst * F1 + f*4],
                   make_float4(v.x*wh, v.y*wh, v.z*wh, v.w*wh));
    }
}

__global__ __launch_bounds__(256) void edge_scatter2(const int* __restrict__ ei) {
    int gwarp = (blockIdx.x * blockDim.x + threadIdx.x) >> 5;
    int lane  = threadIdx.x & 31;
    int e = gwarp * 2 + (lane >> 4);
    int l16 = lane & 15;
    if (e >= NEDGES) return;
    int src = ei[e], dst = ei[NEDGES + e];
    float v = lrelu(g_as2[src] + g_ad2[dst]);
    float w = expf(v - fdec(g_m2[dst]));
    if (l16 == 0) atomicAdd(&g_den2[dst], w);
    float4 hv = *(const float4*)&g_h2[(size_t)src * HIDDEN + l16*4];
    red_add_v4(&g_out2[(size_t)dst * HIDDEN + l16*4],
               make_float4(hv.x*w, hv.y*w, hv.z*w, hv.w*w));
}

// ---------------- normalize + activation ----------------
__global__ __launch_bounds__(256) void normalize1(const float* __restrict__ b1) {
    int idx = blockIdx.x * blockDim.x + threadIdx.x;   // float4 index: N * 64
    if (idx >= NNODES * (F1/4)) return;
    int n = idx >> 6, q = idx & 63;
    int h = q >> 4;
    float d = g_den1[n*HEADS + h] + 1e-16f;
    float4 v = *(float4*)&g_out1[(size_t)n * F1 + q*4];
    float4 b = *(const float4*)&b1[q*4];
    float4 r;
    float tX = v.x / d + b.x; r.x = tX > 0.f ? tX : expm1f(tX);
    float tY = v.y / d + b.y; r.y = tY > 0.f ? tY : expm1f(tY);
    float tZ = v.z / d + b.z; r.z = tZ > 0.f ? tZ : expm1f(tZ);
    float tW = v.w / d + b.w; r.w = tW > 0.f ? tW : expm1f(tW);
    *(float4*)&g_out1[(size_t)n * F1 + q*4] = r;
}

__global__ __launch_bounds__(256) void normalize2(const float* __restrict__ b2) {
    int idx = blockIdx.x * blockDim.x + threadIdx.x;   // float4 index: N * 16
    if (idx >= NNODES * (HIDDEN/4)) return;
    int n = idx >> 4, q = idx & 15;
    float d = g_den2[n] + 1e-16f;
    float4 v = *(float4*)&g_out2[(size_t)n * HIDDEN + q*4];
    float4 b = *(const float4*)&b2[q*4];
    float4 r = make_float4(v.x/d + b.x, v.y/d + b.y, v.z/d + b.z, v.w/d + b.w);
    *(float4*)&g_emb[(size_t)n * HIDDEN + q*4] = r;
}

// ---------------- MLP head: relu(emb@mw1+mb1)@mw2+mb2 ----------------
__global__ __launch_bounds__(256) void mlp_kernel(const float* __restrict__ mw1,
                                                  const float* __restrict__ mb1,
                                                  const float* __restrict__ mw2,
                                                  const float* __restrict__ mb2,
                                                  float* __restrict__ out) {
    __shared__ float w1s[64*64];
    __shared__ float w2s[64*NCLS];
    __shared__ float es[32*64];
    __shared__ float hs[32*64];
    __shared__ float b1s[64];
    __shared__ float b2s[NCLS];
    int t = threadIdx.x;
    for (int i = t; i < 64*64; i += 256) w1s[i] = mw1[i];
    for (int i = t; i < 64*NCLS; i += 256) w2s[i] = mw2[i];
    if (t < 64)  b1s[t] = mb1[t];
    if (t < NCLS) b2s[t] = mb2[t];
    int n0 = blockIdx.x * 32;
    for (int i = t; i < 32*64; i += 256) {
        int n = n0 + (i >> 6);
        es[i] = (n < NNODES) ? g_emb[(size_t)n * 64 + (i & 63)] : 0.f;
    }
    __syncthreads();
    for (int i = t; i < 32*64; i += 256) {
        int n = i >> 6, j = i & 63;
        float a = b1s[j];
#pragma unroll 8
        for (int k = 0; k < 64; k++) a += es[n*64 + k] * w1s[k*64 + j];
        hs[i] = a > 0.f ? a : 0.f;
    }
    __syncthreads();
    for (int i = t; i < 32*NCLS; i += 256) {
        int n = i / NCLS, k = i % NCLS;
        float a = b2s[k];
#pragma unroll 8
        for (int j = 0; j < 64; j++) a += hs[n*64 + j] * w2s[j*NCLS + k];
        int gn = n0 + n;
        if (gn < NNODES) out[(size_t)gn * NCLS + k] = a;
    }
}

// ---------------- launch ----------------
extern "C" void kernel_launch(void* const* d_in, const int* in_sizes, int n_in,
                              void* d_out, int out_size) {
    const float* x        = (const float*)d_in[0];
    const int*   ei       = (const int*)  d_in[1];
    const float* W1       = (const float*)d_in[2];
    const float* att_src1 = (const float*)d_in[3];
    const float* att_dst1 = (const float*)d_in[4];
    const float* b1       = (const float*)d_in[5];
    const float* W2       = (const float*)d_in[6];
    const float* att_src2 = (const float*)d_in[7];
    const float* att_dst2 = (const float*)d_in[8];
    const float* b2       = (const float*)d_in[9];
    const float* mw1      = (const float*)d_in[10];
    const float* mb1      = (const float*)d_in[11];
    const float* mw2      = (const float*)d_in[12];
    const float* mb2      = (const float*)d_in[13];
    float* out = (float*)d_out;

    void *p_h1, *p_out1, *p_m1, *p_den1, *p_h2, *p_out2, *p_m2, *p_den2;
    cudaGetSymbolAddress(&p_h1,  g_h1);
    cudaGetSymbolAddress(&p_out1, g_out1);
    cudaGetSymbolAddress(&p_m1,  g_m1);
    cudaGetSymbolAddress(&p_den1, g_den1);
    cudaGetSymbolAddress(&p_h2,  g_h2);
    cudaGetSymbolAddress(&p_out2, g_out2);
    cudaGetSymbolAddress(&p_m2,  g_m2);
    cudaGetSymbolAddress(&p_den2, g_den2);

    // clear accumulators (encoded -inf for max == 0)
    cudaMemsetAsync(p_m1,   0, sizeof(unsigned)*NNODES*HEADS);
    cudaMemsetAsync(p_den1, 0, sizeof(float)*NNODES*HEADS);
    cudaMemsetAsync(p_out1, 0, sizeof(float)*(size_t)NNODES*F1);
    cudaMemsetAsync(p_m2,   0, sizeof(unsigned)*NNODES);
    cudaMemsetAsync(p_den2, 0, sizeof(float)*NNODES);
    cudaMemsetAsync(p_out2, 0, sizeof(float)*(size_t)NNODES*HIDDEN);

    // ---- layer 1 ----
    {
        dim3 grid(F1/128, (NNODES + 127)/128);
        sgemm<128,128,16,8,8><<<grid, 256>>>(NNODES, F1, INF_, x, W1, (float*)p_h1);
    }
    attn_scores1<<<(NNODES*HEADS + 255)/256, 256>>>(att_src1, att_dst1);
    edge_max1<<<(NEDGES*HEADS + 255)/256, 256>>>(ei);
    edge_scatter1<<<(NEDGES + 7)/8, 256>>>(ei);
    normalize1<<<(NNODES*(F1/4) + 255)/256, 256>>>(b1);

    // ---- layer 2 ----
    {
        dim3 grid(HIDDEN/64, (NNODES + 127)/128);
        sgemm<128,64,16,8,4><<<grid, 256>>>(NNODES, HIDDEN, F1, (const float*)p_out1, W2, (float*)p_h2);
    }
    attn_scores2<<<(NNODES + 255)/256, 256>>>(att_src2, att_dst2);
    edge_max2<<<(NEDGES + 255)/256, 256>>>(ei);
    edge_scatter2<<<((NEDGES + 1)/2 + 7)/8, 256>>>(ei);
    normalize2<<<(NNODES*(HIDDEN/4) + 255)/256, 256>>>(b2);

    // ---- MLP head ----
    mlp_kernel<<<(NNODES + 31)/32, 256>>>(mw1, mb1, mw2, mb2, out);
}

// round 3
// speedup vs baseline: 1.0999x; 1.0999x over previous
#include <cuda_runtime.h>
#include <cstdint>

#define NNODES 50000
#define NEDGES 800000
#define INF_   512
#define HIDDEN 64
#define HEADS  4
#define NCLS   40
#define F1     (HEADS*HIDDEN)   // 256

// ---------------- scratch (device globals; no allocation allowed) ----------------
__device__ float    g_h1 [NNODES*F1];      // x @ W1
__device__ float    g_out1[NNODES*F1];     // layer1 output (elu'd)
__device__ float    g_as1[NNODES*HEADS];
__device__ float    g_ad1[NNODES*HEADS];
__device__ float    g_h2 [NNODES*HIDDEN];  // h @ W2
__device__ float    g_as2[NNODES];
__device__ float    g_ad2[NNODES];
__device__ float    g_emb[NNODES*HIDDEN];
__device__ int      g_deg[NNODES];
__device__ int      g_rowptr[NNODES+1];
__device__ int      g_cursor[NNODES];
__device__ int      g_csr_src[NEDGES];

// ---------------- helpers ----------------
__device__ __forceinline__ float lrelu(float v) { return v > 0.f ? v : 0.2f * v; }

__device__ __forceinline__ unsigned long long pk2(float lo, float hi) {
    unsigned long long r;
    asm("mov.b64 %0, {%1, %2};" : "=l"(r) : "f"(lo), "f"(hi));
    return r;
}
__device__ __forceinline__ void ffma2(unsigned long long& d, unsigned long long a, unsigned long long b) {
    asm("fma.rn.f32x2 %0, %1, %2, %0;" : "+l"(d) : "l"(a), "l"(b));
}
__device__ __forceinline__ float2 upk(unsigned long long v) {
    float2 r;
    asm("mov.b64 {%0, %1}, %2;" : "=f"(r.x), "=f"(r.y) : "l"(v));
    return r;
}

// ================= CSR build =================
__global__ __launch_bounds__(256) void hist_kernel(const int* __restrict__ ei) {
    int e = blockIdx.x * blockDim.x + threadIdx.x;
    if (e < NEDGES) atomicAdd(&g_deg[ei[NEDGES + e]], 1);
}

__global__ __launch_bounds__(1024) void scan_kernel() {
    __shared__ int buf[2][1024];
    const int T = 1024;
    const int per = (NNODES + T - 1) / T;   // 49
    int t = threadIdx.x;
    int beg = t * per;
    int end = beg + per; if (end > NNODES) end = NNODES;
    int sum = 0;
    for (int i = beg; i < end && i < NNODES; i++) sum += g_deg[i];
    buf[0][t] = sum;
    __syncthreads();
    int cur = 0;
    for (int off = 1; off < T; off <<= 1) {
        int v = buf[cur][t];
        if (t >= off) v += buf[cur][t - off];
        buf[cur ^ 1][t] = v;
        cur ^= 1;
        __syncthreads();
    }
    int incl = buf[cur][t];
    int run = incl - sum;   // exclusive prefix
    for (int i = beg; i < end && i < NNODES; i++) {
        g_rowptr[i] = run;
        g_cursor[i] = run;
        run += g_deg[i];
    }
    if (t == T - 1) g_rowptr[NNODES] = incl;
}

__global__ __launch_bounds__(256) void fill_kernel(const int* __restrict__ ei) {
    int e = blockIdx.x * blockDim.x + threadIdx.x;
    if (e >= NEDGES) return;
    int dst = ei[NEDGES + e];
    int pos = atomicAdd(&g_cursor[dst], 1);
    g_csr_src[pos] = ei[e];
}

// ============ f32x2 register-tiled fp32 GEMM: C[M,Nn] = A[M,K] @ B[K,Nn] ============
template<int BM, int BN, int BK, int TM, int TN>
__global__ __launch_bounds__((BM/TM)*(BN/TN))
void sgemm(int M, int Nn, int K,
           const float* __restrict__ A, const float* __restrict__ B, float* __restrict__ C) {
    constexpr int THREADS = (BM/TM)*(BN/TN);
    __shared__ float As[BK][BM];
    __shared__ float Bs[BK][BN];
    const int t  = threadIdx.x;
    const int tx = t % (BN/TN);
    const int ty = t / (BN/TN);
    const int m0 = blockIdx.y * BM;
    const int n0 = blockIdx.x * BN;

    unsigned long long acc2[TM/2][TN];
#pragma unroll
    for (int i = 0; i < TM/2; i++)
#pragma unroll
        for (int j = 0; j < TN; j++) acc2[i][j] = 0ull;

    constexpr int A_LD4 = BM * BK / 4;
    constexpr int B_LD4 = BK * BN / 4;

    for (int k0 = 0; k0 < K; k0 += BK) {
#pragma unroll
        for (int i = t; i < A_LD4; i += THREADS) {
            int row = i / (BK/4), kq = i % (BK/4);
            float4 v = make_float4(0.f, 0.f, 0.f, 0.f);
            int gm = m0 + row;
            if (gm < M) v = *(const float4*)&A[(size_t)gm * K + k0 + kq*4];
            As[kq*4+0][row] = v.x; As[kq*4+1][row] = v.y;
            As[kq*4+2][row] = v.z; As[kq*4+3][row] = v.w;
        }
#pragma unroll
        for (int i = t; i < B_LD4; i += THREADS) {
            int row = i / (BN/4), q = i % (BN/4);
            *(float4*)&Bs[row][q*4] = *(const float4*)&B[(size_t)(k0+row) * Nn + n0 + q*4];
        }
        __syncthreads();
#pragma unroll
        for (int k = 0; k < BK; k++) {
            unsigned long long a2[TM/2];
#pragma unroll
            for (int i = 0; i < TM/2; i++)
                a2[i] = *(const unsigned long long*)&As[k][ty*TM + 2*i];
            float br[TN];
#pragma unroll
            for (int j = 0; j < TN; j += 4)
                *(float4*)&br[j] = *(float4*)&Bs[k][tx*TN + j];
            unsigned long long b2[TN];
#pragma unroll
            for (int j = 0; j < TN; j++) b2[j] = pk2(br[j], br[j]);
#pragma unroll
            for (int i = 0; i < TM/2; i++)
#pragma unroll
                for (int j = 0; j < TN; j++) ffma2(acc2[i][j], a2[i], b2[j]);
        }
        __syncthreads();
    }
#pragma unroll
    for (int i = 0; i < TM/2; i++) {
        float rlo[TN], rhi[TN];
#pragma unroll
        for (int j = 0; j < TN; j++) {
            float2 p = upk(acc2[i][j]);
            rlo[j] = p.x; rhi[j] = p.y;
        }
        int gm = m0 + ty*TM + 2*i;
        if (gm < M) {
#pragma unroll
            for (int j = 0; j < TN; j += 4)
                *(float4*)&C[(size_t)gm * Nn + n0 + tx*TN + j] = *(float4*)&rlo[j];
        }
        if (gm + 1 < M) {
#pragma unroll
            for (int j = 0; j < TN; j += 4)
                *(float4*)&C[(size_t)(gm+1) * Nn + n0 + tx*TN + j] = *(float4*)&rhi[j];
        }
    }
}

// ---------------- attention scores ----------------
__global__ __launch_bounds__(256) void attn_scores1(const float* __restrict__ att_src,
                                                    const float* __restrict__ att_dst) {
    int idx = blockIdx.x * blockDim.x + threadIdx.x;   // n*HEADS + h
    if (idx >= NNODES * HEADS) return;
    int n = idx >> 2, h = idx & 3;
    const float4* hp = (const float4*)&g_h1[(size_t)n * F1 + h * HIDDEN];
    const float4* sp = (const float4*)&att_src[h * HIDDEN];
    const float4* dp = (const float4*)&att_dst[h * HIDDEN];
    float sa = 0.f, da = 0.f;
#pragma unroll
    for (int i = 0; i < HIDDEN/4; i++) {
        float4 v = hp[i], s = sp[i], d = dp[i];
        sa += v.x*s.x + v.y*s.y + v.z*s.z + v.w*s.w;
        da += v.x*d.x + v.y*d.y + v.z*d.z + v.w*d.w;
    }
    g_as1[idx] = sa; g_ad1[idx] = da;
}

__global__ __launch_bounds__(256) void attn_scores2(const float* __restrict__ att_src,
                                                    const float* __restrict__ att_dst) {
    int n = blockIdx.x * blockDim.x + threadIdx.x;
    if (n >= NNODES) return;
    const float4* hp = (const float4*)&g_h2[(size_t)n * HIDDEN];
    const float4* sp = (const float4*)att_src;
    const float4* dp = (const float4*)att_dst;
    float sa = 0.f, da = 0.f;
#pragma unroll
    for (int i = 0; i < HIDDEN/4; i++) {
        float4 v = hp[i], s = sp[i], d = dp[i];
        sa += v.x*s.x + v.y*s.y + v.z*s.z + v.w*s.w;
        da += v.x*d.x + v.y*d.y + v.z*d.z + v.w*d.w;
    }
    g_as2[n] = sa; g_ad2[n] = da;
}

// ============ fused layer-1 gather: softmax + aggregate + normalize + ELU ============
// one warp per dst node; lane holds 8 output floats (head = lane>>3)
__global__ __launch_bounds__(256) void gather1(const float* __restrict__ b1) {
    int warp = (blockIdx.x * blockDim.x + threadIdx.x) >> 5;
    int lane = threadIdx.x & 31;
    if (warp >= NNODES) return;
    const int n = warp;
    const int beg = g_rowptr[n], end = g_rowptr[n+1];
    const int deg = end - beg;
    const int myh = lane >> 3;

    float4 accA = make_float4(0.f,0.f,0.f,0.f);
    float4 accB = make_float4(0.f,0.f,0.f,0.f);
    float4 den  = make_float4(0.f,0.f,0.f,0.f);

    if (deg > 0) {
        float4 adv = *(const float4*)&g_ad1[n*4];
        if (deg <= 32) {
            bool valid = lane < deg;
            int s = valid ? g_csr_src[beg + lane] : 0;
            float4 e = make_float4(-1e30f,-1e30f,-1e30f,-1e30f);
            if (valid) {
                float4 as = *(const float4*)&g_as1[s*4];
                e.x = lrelu(as.x + adv.x); e.y = lrelu(as.y + adv.y);
                e.z = lrelu(as.z + adv.z); e.w = lrelu(as.w + adv.w);
            }
            float4 mx = e;
#pragma unroll
            for (int off = 16; off > 0; off >>= 1) {
                mx.x = fmaxf(mx.x, __shfl_xor_sync(0xffffffffu, mx.x, off));
                mx.y = fmaxf(mx.y, __shfl_xor_sync(0xffffffffu, mx.y, off));
                mx.z = fmaxf(mx.z, __shfl_xor_sync(0xffffffffu, mx.z, off));
                mx.w = fmaxf(mx.w, __shfl_xor_sync(0xffffffffu, mx.w, off));
            }
            float4 w = make_float4(0.f,0.f,0.f,0.f);
            if (valid) {
                w.x = __expf(e.x - mx.x); w.y = __expf(e.y - mx.y);
                w.z = __expf(e.z - mx.z); w.w = __expf(e.w - mx.w);
            }
            den = w;
            for (int j = 0; j < deg; j++) {
                int sj = __shfl_sync(0xffffffffu, s, j);
                float w0 = __shfl_sync(0xffffffffu, w.x, j);
                float w1 = __shfl_sync(0xffffffffu, w.y, j);
                float w2 = __shfl_sync(0xffffffffu, w.z, j);
                float w3 = __shfl_sync(0xffffffffu, w.w, j);
                float myw = myh == 0 ? w0 : myh == 1 ? w1 : myh == 2 ? w2 : w3;
                const float4* hp = (const float4*)&g_h1[(size_t)sj * F1 + lane*8];
                float4 v0 = hp[0], v1 = hp[1];
                accA.x += v0.x*myw; accA.y += v0.y*myw; accA.z += v0.z*myw; accA.w += v0.w*myw;
                accB.x += v1.x*myw; accB.y += v1.y*myw; accB.z += v1.z*myw; accB.w += v1.w*myw;
            }
        } else {
            // pass 1: max
            float4 mx = make_float4(-1e30f,-1e30f,-1e30f,-1e30f);
            for (int p = beg + lane; p < end; p += 32) {
                int s = g_csr_src[p];
                float4 as = *(const float4*)&g_as1[s*4];
                mx.x = fmaxf(mx.x, lrelu(as.x + adv.x));
                mx.y = fmaxf(mx.y, lrelu(as.y + adv.y));
                mx.z = fmaxf(mx.z, lrelu(as.z + adv.z));
                mx.w = fmaxf(mx.w, lrelu(as.w + adv.w));
            }
#pragma unroll
            for (int off = 16; off > 0; off >>= 1) {
                mx.x = fmaxf(mx.x, __shfl_xor_sync(0xffffffffu, mx.x, off));
                mx.y = fmaxf(mx.y, __shfl_xor_sync(0xffffffffu, mx.y, off));
                mx.z = fmaxf(mx.z, __shfl_xor_sync(0xffffffffu, mx.z, off));
                mx.w = fmaxf(mx.w, __shfl_xor_sync(0xffffffffu, mx.w, off));
            }
            // pass 2: exp + accumulate
            for (int p0 = beg; p0 < end; p0 += 32) {
                int p = p0 + lane;
                bool valid = p < end;
                int s = valid ? g_csr_src[p] : 0;
                float4 w = make_float4(0.f,0.f,0.f,0.f);
                if (valid) {
                    float4 as = *(const float4*)&g_as1[s*4];
                    w.x = __expf(lrelu(as.x + adv.x) - mx.x);
                    w.y = __expf(lrelu(as.y + adv.y) - mx.y);
                    w.z = __expf(lrelu(as.z + adv.z) - mx.z);
                    w.w = __expf(lrelu(as.w + adv.w) - mx.w);
                    den.x += w.x; den.y += w.y; den.z += w.z; den.w += w.w;
                }
                int cnt = end - p0; if (cnt > 32) cnt = 32;
                for (int j = 0; j < cnt; j++) {
                    int sj = __shfl_sync(0xffffffffu, s, j);
                    float w0 = __shfl_sync(0xffffffffu, w.x, j);
                    float w1 = __shfl_sync(0xffffffffu, w.y, j);
                    float w2 = __shfl_sync(0xffffffffu, w.z, j);
                    float w3 = __shfl_sync(0xffffffffu, w.w, j);
                    float myw = myh == 0 ? w0 : myh == 1 ? w1 : myh == 2 ? w2 : w3;
                    const float4* hp = (const float4*)&g_h1[(size_t)sj * F1 + lane*8];
                    float4 v0 = hp[0], v1 = hp[1];
                    accA.x += v0.x*myw; accA.y += v0.y*myw; accA.z += v0.z*myw; accA.w += v0.w*myw;
                    accB.x += v1.x*myw; accB.y += v1.y*myw; accB.z += v1.z*myw; accB.w += v1.w*myw;
                }
            }
        }
        // reduce den across warp
#pragma unroll
        for (int off = 16; off > 0; off >>= 1) {
            den.x += __shfl_xor_sync(0xffffffffu, den.x, off);
            den.y += __shfl_xor_sync(0xffffffffu, den.y, off);
            den.z += __shfl_xor_sync(0xffffffffu, den.z, off);
            den.w += __shfl_xor_sync(0xffffffffu, den.w, off);
        }
    }
    float myden = (myh == 0 ? den.x : myh == 1 ? den.y : myh == 2 ? den.z : den.w) + 1e-16f;
    float inv = 1.f / myden;
    float4 bA = *(const float4*)&b1[lane*8];
    float4 bB = *(const float4*)&b1[lane*8 + 4];
    float4 oA, oB;
    float v;
    v = accA.x*inv + bA.x; oA.x = v > 0.f ? v : expm1f(v);
    v = accA.y*inv + bA.y; oA.y = v > 0.f ? v : expm1f(v);
    v = accA.z*inv + bA.z; oA.z = v > 0.f ? v : expm1f(v);
    v = accA.w*inv + bA.w; oA.w = v > 0.f ? v : expm1f(v);
    v = accB.x*inv + bB.x; oB.x = v > 0.f ? v : expm1f(v);
    v = accB.y*inv + bB.y; oB.y = v > 0.f ? v : expm1f(v);
    v = accB.z*inv + bB.z; oB.z = v > 0.f ? v : expm1f(v);
    v = accB.w*inv + bB.w; oB.w = v > 0.f ? v : expm1f(v);
    *(float4*)&g_out1[(size_t)n * F1 + lane*8]     = oA;
    *(float4*)&g_out1[(size_t)n * F1 + lane*8 + 4] = oB;
}

// ============ fused layer-2 gather (heads=1): softmax + aggregate + bias ============
// one warp per dst node; lane holds 2 output floats
__global__ __launch_bounds__(256) void gather2(const float* __restrict__ b2) {
    int warp = (blockIdx.x * blockDim.x + threadIdx.x) >> 5;
    int lane = threadIdx.x & 31;
    if (warp >= NNODES) return;
    const int n = warp;
    const int beg = g_rowptr[n], end = g_rowptr[n+1];
    const int deg = end - beg;

    float2 acc = make_float2(0.f, 0.f);
    float den = 0.f;

    if (deg > 0) {
        float ad = g_ad2[n];
        if (deg <= 32) {
            bool valid = lane < deg;
            int s = valid ? g_csr_src[beg + lane] : 0;
            float e = valid ? lrelu(g_as2[s] + ad) : -1e30f;
            float mx = e;
#pragma unroll
            for (int off = 16; off > 0; off >>= 1)
                mx = fmaxf(mx, __shfl_xor_sync(0xffffffffu, mx, off));
            float w = valid ? __expf(e - mx) : 0.f;
            den = w;
            for (int j = 0; j < deg; j++) {
                int sj = __shfl_sync(0xffffffffu, s, j);
                float wj = __shfl_sync(0xffffffffu, w, j);
                float2 v = *(const float2*)&g_h2[(size_t)sj * HIDDEN + lane*2];
                acc.x += v.x*wj; acc.y += v.y*wj;
            }
        } else {
            float mx = -1e30f;
            for (int p = beg + lane; p < end; p += 32) {
                int s = g_csr_src[p];
                mx = fmaxf(mx, lrelu(g_as2[s] + ad));
            }
#pragma unroll
            for (int off = 16; off > 0; off >>= 1)
                mx = fmaxf(mx, __shfl_xor_sync(0xffffffffu, mx, off));
            for (int p0 = beg; p0 < end; p0 += 32) {
                int p = p0 + lane;
                bool valid = p < end;
                int s = valid ? g_csr_src[p] : 0;
                float w = 0.f;
                if (valid) {
                    w = __expf(lrelu(g_as2[s] + ad) - mx);
                    den += w;
                }
                int cnt = end - p0; if (cnt > 32) cnt = 32;
                for (int j = 0; j < cnt; j++) {
                    int sj = __shfl_sync(0xffffffffu, s, j);
                    float wj = __shfl_sync(0xffffffffu, w, j);
                    float2 v = *(const float2*)&g_h2[(size_t)sj * HIDDEN + lane*2];
                    acc.x += v.x*wj; acc.y += v.y*wj;
                }
            }
        }
#pragma unroll
        for (int off = 16; off > 0; off >>= 1)
            den += __shfl_xor_sync(0xffffffffu, den, off);
    }
    float inv = 1.f / (den + 1e-16f);
    float2 b = *(const float2*)&b2[lane*2];
    float2 o = make_float2(acc.x*inv + b.x, acc.y*inv + b.y);
    *(float2*)&g_emb[(size_t)n * HIDDEN + lane*2] = o;
}

// ---------------- MLP head: relu(emb@mw1+mb1)@mw2+mb2 ----------------
__global__ __launch_bounds__(256) void mlp_kernel(const float* __restrict__ mw1,
                                                  const float* __restrict__ mb1,
                                                  const float* __restrict__ mw2,
                                                  const float* __restrict__ mb2,
                                                  float* __restrict__ out) {
    __shared__ float w1s[64*64];
    __shared__ float w2s[64*NCLS];
    __shared__ float es[32*64];
    __shared__ float hs[32*64];
    __shared__ float b1s[64];
    __shared__ float b2s[NCLS];
    int t = threadIdx.x;
    for (int i = t; i < 64*64; i += 256) w1s[i] = mw1[i];
    for (int i = t; i < 64*NCLS; i += 256) w2s[i] = mw2[i];
    if (t < 64)  b1s[t] = mb1[t];
    if (t < NCLS) b2s[t] = mb2[t];
    int n0 = blockIdx.x * 32;
    for (int i = t; i < 32*64; i += 256) {
        int n = n0 + (i >> 6);
        es[i] = (n < NNODES) ? g_emb[(size_t)n * 64 + (i & 63)] : 0.f;
    }
    __syncthreads();
    for (int i = t; i < 32*64; i += 256) {
        int n = i >> 6, j = i & 63;
        float a = b1s[j];
#pragma unroll 8
        for (int k = 0; k < 64; k++) a += es[n*64 + k] * w1s[k*64 + j];
        hs[i] = a > 0.f ? a : 0.f;
    }
    __syncthreads();
    for (int i = t; i < 32*NCLS; i += 256) {
        int n = i / NCLS, k = i % NCLS;
        float a = b2s[k];
#pragma unroll 8
        for (int j = 0; j < 64; j++) a += hs[n*64 + j] * w2s[j*NCLS + k];
        int gn = n0 + n;
        if (gn < NNODES) out[(size_t)gn * NCLS + k] = a;
    }
}

// ---------------- launch ----------------
extern "C" void kernel_launch(void* const* d_in, const int* in_sizes, int n_in,
                              void* d_out, int out_size) {
    const float* x        = (const float*)d_in[0];
    const int*   ei       = (const int*)  d_in[1];
    const float* W1       = (const float*)d_in[2];
    const float* att_src1 = (const float*)d_in[3];
    const float* att_dst1 = (const float*)d_in[4];
    const float* b1       = (const float*)d_in[5];
    const float* W2       = (const float*)d_in[6];
    const float* att_src2 = (const float*)d_in[7];
    const float* att_dst2 = (const float*)d_in[8];
    const float* b2       = (const float*)d_in[9];
    const float* mw1      = (const float*)d_in[10];
    const float* mb1      = (const float*)d_in[11];
    const float* mw2      = (const float*)d_in[12];
    const float* mb2      = (const float*)d_in[13];
    float* out = (float*)d_out;

    void *p_h1, *p_out1, *p_h2, *p_deg;
    cudaGetSymbolAddress(&p_h1,   g_h1);
    cudaGetSymbolAddress(&p_out1, g_out1);
    cudaGetSymbolAddress(&p_h2,   g_h2);
    cudaGetSymbolAddress(&p_deg,  g_deg);

    // ---- CSR build (independent of features) ----
    cudaMemsetAsync(p_deg, 0, sizeof(int)*NNODES);
    hist_kernel<<<(NEDGES + 255)/256, 256>>>(ei);
    scan_kernel<<<1, 1024>>>();
    fill_kernel<<<(NEDGES + 255)/256, 256>>>(ei);

    // ---- layer 1 ----
    {
        dim3 grid(F1/128, (NNODES + 127)/128);
        sgemm<128,128,16,8,8><<<grid, 256>>>(NNODES, F1, INF_, x, W1, (float*)p_h1);
    }
    attn_scores1<<<(NNODES*HEADS + 255)/256, 256>>>(att_src1, att_dst1);
    gather1<<<(NNODES*32 + 255)/256, 256>>>(b1);

    // ---- layer 2 ----
    {
        dim3 grid(HIDDEN/64, (NNODES + 127)/128);
        sgemm<128,64,16,8,4><<<grid, 256>>>(NNODES, HIDDEN, F1, (const float*)p_out1, W2, (float*)p_h2);
    }
    attn_scores2<<<(NNODES + 255)/256, 256>>>(att_src2, att_dst2);
    gather2<<<(NNODES*32 + 255)/256, 256>>>(b2);

    // ---- MLP head ----
    mlp_kernel<<<(NNODES + 31)/32, 256>>>(mw1, mb1, mw2, mb2, out);
}

// round 9
// speedup vs baseline: 1.5564x; 1.4150x over previous
#include <cuda_runtime.h>
#include <cuda_bf16.h>
#include <cstdint>

#define NNODES 50000
#define NEDGES 800000
#define INF_   512
#define HIDDEN 64
#define HEADS  4
#define NCLS   40
#define F1     (HEADS*HIDDEN)   // 256

// ---------------- scratch (device globals; no allocation allowed) ----------------
__device__ __align__(16) __nv_bfloat16 g_xhi[(size_t)NNODES*INF_];
__device__ __align__(16) __nv_bfloat16 g_xlo[(size_t)NNODES*INF_];
__device__ __align__(16) __nv_bfloat16 g_w1t_hi[F1*INF_];   // [N=256, K=512]
__device__ __align__(16) __nv_bfloat16 g_w1t_lo[F1*INF_];
__device__ __align__(16) float g_h1 [(size_t)NNODES*F1];    // x @ W1 (f32)
__device__ __align__(16) __nv_bfloat16 g_o1hi[(size_t)NNODES*F1];  // elu(out1) split
__device__ __align__(16) __nv_bfloat16 g_o1lo[(size_t)NNODES*F1];
__device__ __align__(16) __nv_bfloat16 g_w2t_hi[HIDDEN*F1]; // [N=64, K=256]
__device__ __align__(16) __nv_bfloat16 g_w2t_lo[HIDDEN*F1];
__device__ __align__(16) float g_h2 [(size_t)NNODES*HIDDEN];
__device__ float g_as1[NNODES*HEADS];
__device__ float g_ad1[NNODES*HEADS];
__device__ float g_as2[NNODES];
__device__ float g_ad2[NNODES];
__device__ __align__(16) float g_emb[(size_t)NNODES*HIDDEN];
__device__ int g_deg[NNODES];
__device__ int g_rowptr[NNODES+1];
__device__ int g_cursor[NNODES];
__device__ int g_csr_src[NEDGES];

// ---------------- helpers ----------------
__device__ __forceinline__ float lrelu(float v) { return v > 0.f ? v : 0.2f * v; }
__device__ __forceinline__ uint32_t smem_u32(const void* p) {
    return (uint32_t)__cvta_generic_to_shared(p);
}
__device__ __forceinline__ uint32_t swz128(uint32_t off) { return off ^ ((off >> 3) & 0x70); }

__device__ __forceinline__ void cp16(uint32_t dst, const void* src, bool v) {
    asm volatile("cp.async.cg.shared.global [%0], [%1], 16, %2;"
                 :: "r"(dst), "l"(src), "r"(v ? 16 : 0) : "memory");
}

__device__ __forceinline__ void ldsm_x4(uint32_t (&r)[4], uint32_t addr) {
    asm volatile("ldmatrix.sync.aligned.m8n8.x4.shared.b16 {%0,%1,%2,%3}, [%4];"
                 : "=r"(r[0]), "=r"(r[1]), "=r"(r[2]), "=r"(r[3]) : "r"(addr));
}
__device__ __forceinline__ void ldsm_x2(uint32_t (&r)[2], uint32_t addr) {
    asm volatile("ldmatrix.sync.aligned.m8n8.x2.shared.b16 {%0,%1}, [%2];"
                 : "=r"(r[0]), "=r"(r[1]) : "r"(addr));
}
__device__ __forceinline__ void mma16816(float (&d)[4], const uint32_t (&a)[4],
                                         const uint32_t (&b)[2]) {
    asm volatile(
        "mma.sync.aligned.m16n8k16.row.col.f32.bf16.bf16.f32 "
        "{%0,%1,%2,%3}, {%4,%5,%6,%7}, {%8,%9}, {%0,%1,%2,%3};"
        : "+f"(d[0]), "+f"(d[1]), "+f"(d[2]), "+f"(d[3])
        : "r"(a[0]), "r"(a[1]), "r"(a[2]), "r"(a[3]), "r"(b[0]), "r"(b[1]));
}

// ================= fp32 -> bf16 hi/lo split =================
__device__ __forceinline__ void split1(float v, unsigned short& h, unsigned short& l) {
    __nv_bfloat16 hb = __float2bfloat16(v);
    __nv_bfloat16 lb = __float2bfloat16(v - __bfloat162float(hb));
    h = __bfloat16_as_ushort(hb);
    l = __bfloat16_as_ushort(lb);
}

__global__ __launch_bounds__(256) void split_kernel(const float* __restrict__ src,
                                                    __nv_bfloat16* __restrict__ hi,
                                                    __nv_bfloat16* __restrict__ lo, int n4) {
    int i = blockIdx.x * blockDim.x + threadIdx.x;
    if (i >= n4) return;
    float4 v = ((const float4*)src)[i];
    unsigned short h0,h1,h2,h3,l0,l1,l2,l3;
    split1(v.x,h0,l0); split1(v.y,h1,l1); split1(v.z,h2,l2); split1(v.w,h3,l3);
    uint2 H = make_uint2((uint32_t)h0 | ((uint32_t)h1 << 16), (uint32_t)h2 | ((uint32_t)h3 << 16));
    uint2 L = make_uint2((uint32_t)l0 | ((uint32_t)l1 << 16), (uint32_t)l2 | ((uint32_t)l3 << 16));
    ((uint2*)hi)[i] = H;
    ((uint2*)lo)[i] = L;
}

// transpose + split: W[K,N] -> out[N,K]
__global__ void splitT_kernel(const float* __restrict__ W,
                              __nv_bfloat16* __restrict__ hiT,
                              __nv_bfloat16* __restrict__ loT, int K, int N) {
    __shared__ float t[32][33];
    int bn = blockIdx.x * 32, bk = blockIdx.y * 32;
    int tx = threadIdx.x, ty = threadIdx.y;   // 32 x 8
    for (int r = ty; r < 32; r += 8)
        t[r][tx] = W[(size_t)(bk + r) * N + bn + tx];
    __syncthreads();
    for (int r = ty; r < 32; r += 8) {
        float v = t[tx][r];   // W[bk+tx][bn+r]
        unsigned short h, l;
        split1(v, h, l);
        hiT[(size_t)(bn + r) * K + bk + tx] = __ushort_as_bfloat16(h);
        loT[(size_t)(bn + r) * K + bk + tx] = __ushort_as_bfloat16(l);
    }
}

// ========= mma.sync split-bf16 GEMM: C[M,N] = A[M,K] @ B[N,K]^T (3-term compensated) =========
// BM=128 fixed, 8 warps (2 warpM x 4 warpN). KC=64 per chunk, SW128-swizzled smem, cp.async 2-stage.
template<int BN>
__global__ __launch_bounds__(256, 1)
void mma_gemm(const __nv_bfloat16* __restrict__ Ahi, const __nv_bfloat16* __restrict__ Alo,
              const __nv_bfloat16* __restrict__ Bhi, const __nv_bfloat16* __restrict__ Blo,
              float* __restrict__ C, int M, int N, int Ktot) {
    constexpr int NFRAG = BN / 32;        // n-frags of 8 per warp (warp covers BN/4 cols)
    constexpr int A_BYTES = 128 * 128;    // 16KB per half (128 rows x 64 bf16)
    constexpr int B_BYTES = BN * 128;
    constexpr int STAGE = 2 * A_BYTES + 2 * B_BYTES;

    extern __shared__ char dsmem[];
    uint32_t base = (smem_u32(dsmem) + 1023) & ~1023u;

    const int tid = threadIdx.x;
    const int wid = tid >> 5, lane = tid & 31;
    const int warpM = wid >> 2, warpN = wid & 3;
    const int m0 = blockIdx.y * 128;
    const int n0 = blockIdx.x * BN;

    float acc[4][NFRAG][4];
#pragma unroll
    for (int mf = 0; mf < 4; mf++)
#pragma unroll
        for (int nf = 0; nf < NFRAG; nf++)
#pragma unroll
            for (int r = 0; r < 4; r++) acc[mf][nf][r] = 0.f;

    const int C_CH = Ktot / 64;

    auto load_chunk = [&](int i, uint32_t st) {
        int k0 = i * 64;
        // A: 2 halves x 128 rows x 8 x 16B
#pragma unroll
        for (int idx = tid; idx < 2048; idx += 256) {
            int half = idx >> 10, c = idx & 1023;
            int row = c >> 3, q = c & 7;
            const __nv_bfloat16* sb = half ? Alo : Ahi;
            bool v = (m0 + row) < M;
            const void* src = sb + ((size_t)(v ? m0 + row : 0) * Ktot + k0 + q * 8);
            cp16(st + half * A_BYTES + swz128(row * 128 + q * 16), src, v);
        }
        // B: 2 halves x BN rows x 8 x 16B
#pragma unroll
        for (int idx = tid; idx < BN * 16; idx += 256) {
            int half = (idx >= BN * 8) ? 1 : 0;
            int c = idx - half * BN * 8;
            int row = c >> 3, q = c & 7;
            const __nv_bfloat16* sb = half ? Blo : Bhi;
            const void* src = sb + ((size_t)(n0 + row) * Ktot + k0 + q * 8);
            cp16(st + 2 * A_BYTES + half * B_BYTES + swz128(row * 128 + q * 16), src, true);
        }
        asm volatile("cp.async.commit_group;" ::: "memory");
    };

    load_chunk(0, base);

    // per-lane ldmatrix row indices
    const int a_row = warpM * 64 + (lane & 15);      // + mf*16
    const int a_k16 = (lane >> 4) * 16;              // byte offset of k-half
    const int b_row = warpN * (NFRAG * 8) + (lane & 7);  // + nf*8
    const int b_k16 = ((lane >> 3) & 1) * 16;

    for (int i = 0; i < C_CH; i++) {
        uint32_t st = base + (i & 1) * STAGE;
        if (i + 1 < C_CH) {
            load_chunk(i + 1, base + ((i + 1) & 1) * STAGE);
            asm volatile("cp.async.wait_group 1;" ::: "memory");
        } else {
            asm volatile("cp.async.wait_group 0;" ::: "memory");
        }
        __syncthreads();

        uint32_t sAh = st, sAl = st + A_BYTES;
        uint32_t sBh = st + 2 * A_BYTES, sBl = sBh + B_BYTES;

#pragma unroll
        for (int kk = 0; kk < 4; kk++) {
            int kb = kk * 32;   // 16 bf16 per k-step = 32 bytes
            uint32_t ah[4][4], al[4][4];
#pragma unroll
            for (int mf = 0; mf < 4; mf++) {
                uint32_t off = swz128((uint32_t)(a_row + mf * 16) * 128 + kb + a_k16);
                ldsm_x4(ah[mf], sAh + off);
                ldsm_x4(al[mf], sAl + off);
            }
            uint32_t bh[NFRAG][2], bl[NFRAG][2];
#pragma unroll
            for (int nf = 0; nf < NFRAG; nf++) {
                uint32_t off = swz128((uint32_t)(b_row + nf * 8) * 128 + kb + b_k16);
                ldsm_x2(bh[nf], sBh + off);
                ldsm_x2(bl[nf], sBl + off);
            }
#pragma unroll
            for (int mf = 0; mf < 4; mf++)
#pragma unroll
                for (int nf = 0; nf < NFRAG; nf++) {
                    mma16816(acc[mf][nf], ah[mf], bh[nf]);
                    mma16816(acc[mf][nf], ah[mf], bl[nf]);
                    mma16816(acc[mf][nf], al[mf], bh[nf]);
                }
        }
        __syncthreads();
    }

    // epilogue: fragment layout -> C
    const int mr = m0 + warpM * 64 + (lane >> 2);
    const int nc = n0 + warpN * (NFRAG * 8) + (lane & 3) * 2;
#pragma unroll
    for (int mf = 0; mf < 4; mf++) {
        int r0 = mr + mf * 16;
#pragma unroll
        for (int nf = 0; nf < NFRAG; nf++) {
            int cidx = nc + nf * 8;
            if (r0 < M)
                *(float2*)&C[(size_t)r0 * N + cidx] = make_float2(acc[mf][nf][0], acc[mf][nf][1]);
            if (r0 + 8 < M)
                *(float2*)&C[(size_t)(r0 + 8) * N + cidx] = make_float2(acc[mf][nf][2], acc[mf][nf][3]);
        }
    }
}

// ================= CSR build =================
__global__ __launch_bounds__(256) void hist_kernel(const int* __restrict__ ei) {
    int e = blockIdx.x * blockDim.x + threadIdx.x;
    if (e < NEDGES) atomicAdd(&g_deg[ei[NEDGES + e]], 1);
}

__global__ __launch_bounds__(1024) void scan_kernel() {
    __shared__ int buf[2][1024];
    const int T = 1024;
    const int per = (NNODES + T - 1) / T;
    int t = threadIdx.x;
    int beg = t * per;
    int end = beg + per; if (end > NNODES) end = NNODES;
    int sum = 0;
    for (int i = beg; i < end && i < NNODES; i++) sum += g_deg[i];
    buf[0][t] = sum;
    __syncthreads();
    int cur = 0;
    for (int off = 1; off < T; off <<= 1) {
        int v = buf[cur][t];
        if (t >= off) v += buf[cur][t - off];
        buf[cur ^ 1][t] = v;
        cur ^= 1;
        __syncthreads();
    }
    int incl = buf[cur][t];
    int run = incl - sum;
    for (int i = beg; i < end && i < NNODES; i++) {
        g_rowptr[i] = run;
        g_cursor[i] = run;
        run += g_deg[i];
    }
    if (t == T - 1) g_rowptr[NNODES] = incl;
}

__global__ __launch_bounds__(256) void fill_kernel(const int* __restrict__ ei) {
    int e = blockIdx.x * blockDim.x + threadIdx.x;
    if (e >= NEDGES) return;
    int dst = ei[NEDGES + e];
    int pos = atomicAdd(&g_cursor[dst], 1);
    g_csr_src[pos] = ei[e];
}

// ---------------- attention scores ----------------
__global__ __launch_bounds__(256) void attn_scores1(const float* __restrict__ att_src,
                                                    const float* __restrict__ att_dst) {
    int idx = blockIdx.x * blockDim.x + threadIdx.x;
    if (idx >= NNODES * HEADS) return;
    int n = idx >> 2, h = idx & 3;
    const float4* hp = (const float4*)&g_h1[(size_t)n * F1 + h * HIDDEN];
    const float4* sp = (const float4*)&att_src[h * HIDDEN];
    const float4* dp = (const float4*)&att_dst[h * HIDDEN];
    float sa = 0.f, da = 0.f;
#pragma unroll
    for (int i = 0; i < HIDDEN/4; i++) {
        float4 v = hp[i], s = sp[i], d = dp[i];
        sa += v.x*s.x + v.y*s.y + v.z*s.z + v.w*s.w;
        da += v.x*d.x + v.y*d.y + v.z*d.z + v.w*d.w;
    }
    g_as1[idx] = sa; g_ad1[idx] = da;
}

__global__ __launch_bounds__(256) void attn_scores2(const float* __restrict__ att_src,
                                                    const float* __restrict__ att_dst) {
    int n = blockIdx.x * blockDim.x + threadIdx.x;
    if (n >= NNODES) return;
    const float4* hp = (const float4*)&g_h2[(size_t)n * HIDDEN];
    const float4* sp = (const float4*)att_src;
    const float4* dp = (const float4*)att_dst;
    float sa = 0.f, da = 0.f;
#pragma unroll
    for (int i = 0; i < HIDDEN/4; i++) {
        float4 v = hp[i], s = sp[i], d = dp[i];
        sa += v.x*s.x + v.y*s.y + v.z*s.z + v.w*s.w;
        da += v.x*d.x + v.y*d.y + v.z*d.z + v.w*d.w;
    }
    g_as2[n] = sa; g_ad2[n] = da;
}

// ============ fused layer-1 gather: softmax + aggregate + normalize + ELU -> bf16 split ============
__global__ __launch_bounds__(256) void gather1(const float* __restrict__ b1) {
    int warp = (blockIdx.x * blockDim.x + threadIdx.x) >> 5;
    int lane = threadIdx.x & 31;
    if (warp >= NNODES) return;
    const int n = warp;
    const int beg = g_rowptr[n], end = g_rowptr[n+1];
    const int deg = end - beg;
    const int myh = lane >> 3;

    float4 accA = make_float4(0.f,0.f,0.f,0.f);
    float4 accB = make_float4(0.f,0.f,0.f,0.f);
    float4 den  = make_float4(0.f,0.f,0.f,0.f);

    if (deg > 0) {
        float4 adv = *(const float4*)&g_ad1[n*4];
        if (deg <= 32) {
            bool valid = lane < deg;
            int s = valid ? g_csr_src[beg + lane] : 0;
            float4 e = make_float4(-1e30f,-1e30f,-1e30f,-1e30f);
            if (valid) {
                float4 as = *(const float4*)&g_as1[s*4];
                e.x = lrelu(as.x + adv.x); e.y = lrelu(as.y + adv.y);
                e.z = lrelu(as.z + adv.z); e.w = lrelu(as.w + adv.w);
            }
            float4 mx = e;
#pragma unroll
            for (int off = 16; off > 0; off >>= 1) {
                mx.x = fmaxf(mx.x, __shfl_xor_sync(0xffffffffu, mx.x, off));
                mx.y = fmaxf(mx.y, __shfl_xor_sync(0xffffffffu, mx.y, off));
                mx.z = fmaxf(mx.z, __shfl_xor_sync(0xffffffffu, mx.z, off));
                mx.w = fmaxf(mx.w, __shfl_xor_sync(0xffffffffu, mx.w, off));
            }
            float4 w = make_float4(0.f,0.f,0.f,0.f);
            if (valid) {
                w.x = __expf(e.x - mx.x); w.y = __expf(e.y - mx.y);
                w.z = __expf(e.z - mx.z); w.w = __expf(e.w - mx.w);
            }
            den = w;
            for (int j = 0; j < deg; j++) {
                int sj = __shfl_sync(0xffffffffu, s, j);
                float w0 = __shfl_sync(0xffffffffu, w.x, j);
                float w1 = __shfl_sync(0xffffffffu, w.y, j);
                float w2 = __shfl_sync(0xffffffffu, w.z, j);
                float w3 = __shfl_sync(0xffffffffu, w.w, j);
                float myw = myh == 0 ? w0 : myh == 1 ? w1 : myh == 2 ? w2 : w3;
                const float4* hp = (const float4*)&g_h1[(size_t)sj * F1 + lane*8];
                float4 v0 = hp[0], v1 = hp[1];
                accA.x += v0.x*myw; accA.y += v0.y*myw; accA.z += v0.z*myw; accA.w += v0.w*myw;
                accB.x += v1.x*myw; accB.y += v1.y*myw; accB.z += v1.z*myw; accB.w += v1.w*myw;
            }
        } else {
            float4 mx = make_float4(-1e30f,-1e30f,-1e30f,-1e30f);
            for (int p = beg + lane; p < end; p += 32) {
                int s = g_csr_src[p];
                float4 as = *(const float4*)&g_as1[s*4];
                mx.x = fmaxf(mx.x, lrelu(as.x + adv.x));
                mx.y = fmaxf(mx.y, lrelu(as.y + adv.y));
                mx.z = fmaxf(mx.z, lrelu(as.z + adv.z));
                mx.w = fmaxf(mx.w, lrelu(as.w + adv.w));
            }
#pragma unroll
            for (int off = 16; off > 0; off >>= 1) {
                mx.x = fmaxf(mx.x, __shfl_xor_sync(0xffffffffu, mx.x, off));
                mx.y = fmaxf(mx.y, __shfl_xor_sync(0xffffffffu, mx.y, off));
                mx.z = fmaxf(mx.z, __shfl_xor_sync(0xffffffffu, mx.z, off));
                mx.w = fmaxf(mx.w, __shfl_xor_sync(0xffffffffu, mx.w, off));
            }
            for (int p0 = beg; p0 < end; p0 += 32) {
                int p = p0 + lane;
                bool valid = p < end;
                int s = valid ? g_csr_src[p] : 0;
                float4 w = make_float4(0.f,0.f,0.f,0.f);
                if (valid) {
                    float4 as = *(const float4*)&g_as1[s*4];
                    w.x = __expf(lrelu(as.x + adv.x) - mx.x);
                    w.y = __expf(lrelu(as.y + adv.y) - mx.y);
                    w.z = __expf(lrelu(as.z + adv.z) - mx.z);
                    w.w = __expf(lrelu(as.w + adv.w) - mx.w);
                    den.x += w.x; den.y += w.y; den.z += w.z; den.w += w.w;
                }
                int cnt = end - p0; if (cnt > 32) cnt = 32;
                for (int j = 0; j < cnt; j++) {
                    int sj = __shfl_sync(0xffffffffu, s, j);
                    float w0 = __shfl_sync(0xffffffffu, w.x, j);
                    float w1 = __shfl_sync(0xffffffffu, w.y, j);
                    float w2 = __shfl_sync(0xffffffffu, w.z, j);
                    float w3 = __shfl_sync(0xffffffffu, w.w, j);
                    float myw = myh == 0 ? w0 : myh == 1 ? w1 : myh == 2 ? w2 : w3;
                    const float4* hp = (const float4*)&g_h1[(size_t)sj * F1 + lane*8];
                    float4 v0 = hp[0], v1 = hp[1];
                    accA.x += v0.x*myw; accA.y += v0.y*myw; accA.z += v0.z*myw; accA.w += v0.w*myw;
                    accB.x += v1.x*myw; accB.y += v1.y*myw; accB.z += v1.z*myw; accB.w += v1.w*myw;
                }
            }
        }
#pragma unroll
        for (int off = 16; off > 0; off >>= 1) {
            den.x += __shfl_xor_sync(0xffffffffu, den.x, off);
            den.y += __shfl_xor_sync(0xffffffffu, den.y, off);
            den.z += __shfl_xor_sync(0xffffffffu, den.z, off);
            den.w += __shfl_xor_sync(0xffffffffu, den.w, off);
        }
    }
    float myden = (myh == 0 ? den.x : myh == 1 ? den.y : myh == 2 ? den.z : den.w) + 1e-16f;
    float inv = 1.f / myden;
    float4 bA = *(const float4*)&b1[lane*8];
    float4 bB = *(const float4*)&b1[lane*8 + 4];
    float o[8];
    float v;
    v = accA.x*inv + bA.x; o[0] = v > 0.f ? v : expm1f(v);
    v = accA.y*inv + bA.y; o[1] = v > 0.f ? v : expm1f(v);
    v = accA.z*inv + bA.z; o[2] = v > 0.f ? v : expm1f(v);
    v = accA.w*inv + bA.w; o[3] = v > 0.f ? v : expm1f(v);
    v = accB.x*inv + bB.x; o[4] = v > 0.f ? v : expm1f(v);
    v = accB.y*inv + bB.y; o[5] = v > 0.f ? v : expm1f(v);
    v = accB.z*inv + bB.z; o[6] = v > 0.f ? v : expm1f(v);
    v = accB.w*inv + bB.w; o[7] = v > 0.f ? v : expm1f(v);
    unsigned short hs[8], ls[8];
#pragma unroll
    for (int j = 0; j < 8; j++) split1(o[j], hs[j], ls[j]);
    uint4 H = make_uint4((uint32_t)hs[0] | ((uint32_t)hs[1] << 16),
                         (uint32_t)hs[2] | ((uint32_t)hs[3] << 16),
                         (uint32_t)hs[4] | ((uint32_t)hs[5] << 16),
                         (uint32_t)hs[6] | ((uint32_t)hs[7] << 16));
    uint4 L = make_uint4((uint32_t)ls[0] | ((uint32_t)ls[1] << 16),
                         (uint32_t)ls[2] | ((uint32_t)ls[3] << 16),
                         (uint32_t)ls[4] | ((uint32_t)ls[5] << 16),
                         (uint32_t)ls[6] | ((uint32_t)ls[7] << 16));
    *(uint4*)&g_o1hi[(size_t)n * F1 + lane*8] = H;
    *(uint4*)&g_o1lo[(size_t)n * F1 + lane*8] = L;
}

// ============ fused layer-2 gather (heads=1) ============
__global__ __launch_bounds__(256) void gather2(const float* __restrict__ b2) {
    int warp = (blockIdx.x * blockDim.x + threadIdx.x) >> 5;
    int lane = threadIdx.x & 31;
    if (warp >= NNODES) return;
    const int n = warp;
    const int beg = g_rowptr[n], end = g_rowptr[n+1];
    const int deg = end - beg;

    float2 acc = make_float2(0.f, 0.f);
    float den = 0.f;

    if (deg > 0) {
        float ad = g_ad2[n];
        if (deg <= 32) {
            bool valid = lane < deg;
            int s = valid ? g_csr_src[beg + lane] : 0;
            float e = valid ? lrelu(g_as2[s] + ad) : -1e30f;
            float mx = e;
#pragma unroll
            for (int off = 16; off > 0; off >>= 1)
                mx = fmaxf(mx, __shfl_xor_sync(0xffffffffu, mx, off));
            float w = valid ? __expf(e - mx) : 0.f;
            den = w;
            for (int j = 0; j < deg; j++) {
                int sj = __shfl_sync(0xffffffffu, s, j);
                float wj = __shfl_sync(0xffffffffu, w, j);
                float2 v = *(const float2*)&g_h2[(size_t)sj * HIDDEN + lane*2];
                acc.x += v.x*wj; acc.y += v.y*wj;
            }
        } else {
            float mx = -1e30f;
            for (int p = beg + lane; p < end; p += 32) {
                int s = g_csr_src[p];
                mx = fmaxf(mx, lrelu(g_as2[s] + ad));
            }
#pragma unroll
            for (int off = 16; off > 0; off >>= 1)
                mx = fmaxf(mx, __shfl_xor_sync(0xffffffffu, mx, off));
            for (int p0 = beg; p0 < end; p0 += 32) {
                int p = p0 + lane;
                bool valid = p < end;
                int s = valid ? g_csr_src[p] : 0;
                float w = 0.f;
                if (valid) {
                    w = __expf(lrelu(g_as2[s] + ad) - mx);
                    den += w;
                }
                int cnt = end - p0; if (cnt > 32) cnt = 32;
                for (int j = 0; j < cnt; j++) {
                    int sj = __shfl_sync(0xffffffffu, s, j);
                    float wj = __shfl_sync(0xffffffffu, w, j);
                    float2 v = *(const float2*)&g_h2[(size_t)sj * HIDDEN + lane*2];
                    acc.x += v.x*wj; acc.y += v.y*wj;
                }
            }
        }
#pragma unroll
        for (int off = 16; off > 0; off >>= 1)
            den += __shfl_xor_sync(0xffffffffu, den, off);
    }
    float inv = 1.f / (den + 1e-16f);
    float2 b = *(const float2*)&b2[lane*2];
    float2 o = make_float2(acc.x*inv + b.x, acc.y*inv + b.y);
    *(float2*)&g_emb[(size_t)n * HIDDEN + lane*2] = o;
}

// ---------------- MLP head ----------------
__global__ __launch_bounds__(256) void mlp_kernel(const float* __restrict__ mw1,
                                                  const float* __restrict__ mb1,
                                                  const float* __restrict__ mw2,
                                                  const float* __restrict__ mb2,
                                                  float* __restrict__ out) {
    __shared__ float w1s[64*64];
    __shared__ float w2s[64*NCLS];
    __shared__ float es[32*64];
    __shared__ float hs[32*64];
    __shared__ float b1s[64];
    __shared__ float b2s[NCLS];
    int t = threadIdx.x;
    for (int i = t; i < 64*64; i += 256) w1s[i] = mw1[i];
    for (int i = t; i < 64*NCLS; i += 256) w2s[i] = mw2[i];
    if (t < 64)  b1s[t] = mb1[t];
    if (t < NCLS) b2s[t] = mb2[t];
    int n0 = blockIdx.x * 32;
    for (int i = t; i < 32*64; i += 256) {
        int n = n0 + (i >> 6);
        es[i] = (n < NNODES) ? g_emb[(size_t)n * 64 + (i & 63)] : 0.f;
    }
    __syncthreads();
    for (int i = t; i < 32*64; i += 256) {
        int n = i >> 6, j = i & 63;
        float a = b1s[j];
#pragma unroll 8
        for (int k = 0; k < 64; k++) a += es[n*64 + k] * w1s[k*64 + j];
        hs[i] = a > 0.f ? a : 0.f;
    }
    __syncthreads();
    for (int i = t; i < 32*NCLS; i += 256) {
        int n = i / NCLS, k = i % NCLS;
        float a = b2s[k];
#pragma unroll 8
        for (int j = 0; j < 64; j++) a += hs[n*64 + j] * w2s[j*NCLS + k];
        int gn = n0 + n;
        if (gn < NNODES) out[(size_t)gn * NCLS + k] = a;
    }
}

// ---------------- launch ----------------
extern "C" void kernel_launch(void* const* d_in, const int* in_sizes, int n_in,
                              void* d_out, int out_size) {
    const float* x        = (const float*)d_in[0];
    const int*   ei       = (const int*)  d_in[1];
    const float* W1       = (const float*)d_in[2];
    const float* att_src1 = (const float*)d_in[3];
    const float* att_dst1 = (const float*)d_in[4];
    const float* b1       = (const float*)d_in[5];
    const float* W2       = (const float*)d_in[6];
    const float* att_src2 = (const float*)d_in[7];
    const float* att_dst2 = (const float*)d_in[8];
    const float* b2       = (const float*)d_in[9];
    const float* mw1      = (const float*)d_in[10];
    const float* mb1      = (const float*)d_in[11];
    const float* mw2      = (const float*)d_in[12];
    const float* mb2      = (const float*)d_in[13];
    float* out = (float*)d_out;

    void *p_deg, *p_xhi, *p_xlo, *p_w1h, *p_w1l, *p_h1, *p_o1h, *p_o1l, *p_w2h, *p_w2l, *p_h2;
    cudaGetSymbolAddress(&p_deg, g_deg);
    cudaGetSymbolAddress(&p_xhi, g_xhi);  cudaGetSymbolAddress(&p_xlo, g_xlo);
    cudaGetSymbolAddress(&p_w1h, g_w1t_hi); cudaGetSymbolAddress(&p_w1l, g_w1t_lo);
    cudaGetSymbolAddress(&p_h1,  g_h1);
    cudaGetSymbolAddress(&p_o1h, g_o1hi);  cudaGetSymbolAddress(&p_o1l, g_o1lo);
    cudaGetSymbolAddress(&p_w2h, g_w2t_hi); cudaGetSymbolAddress(&p_w2l, g_w2t_lo);
    cudaGetSymbolAddress(&p_h2,  g_h2);

    // stage = 2*A(16KB) + 2*B(BN*128B); double-buffered + 1KB align slack
    constexpr int SMEM1 = 2 * (2*128*128 + 2*128*128) + 1024;   // BN=128 -> 132096
    constexpr int SMEM2 = 2 * (2*128*128 + 2*64*128) + 1024;    // BN=64  -> 99328
    cudaFuncSetAttribute((const void*)&mma_gemm<128>, cudaFuncAttributeMaxDynamicSharedMemorySize, SMEM1);
    cudaFuncSetAttribute((const void*)&mma_gemm<64>,  cudaFuncAttributeMaxDynamicSharedMemorySize, SMEM2);

    // ---- CSR build ----
    cudaMemsetAsync(p_deg, 0, sizeof(int)*NNODES);
    hist_kernel<<<(NEDGES + 255)/256, 256>>>(ei);
    scan_kernel<<<1, 1024>>>();
    fill_kernel<<<(NEDGES + 255)/256, 256>>>(ei);

    // ---- operand conversions ----
    {
        int n4 = NNODES * INF_ / 4;
        split_kernel<<<(n4 + 255)/256, 256>>>(x, (__nv_bfloat16*)p_xhi, (__nv_bfloat16*)p_xlo, n4);
        dim3 thr(32, 8);
        splitT_kernel<<<dim3(F1/32, INF_/32), thr>>>(W1, (__nv_bfloat16*)p_w1h, (__nv_bfloat16*)p_w1l, INF_, F1);
        splitT_kernel<<<dim3(HIDDEN/32, F1/32), thr>>>(W2, (__nv_bfloat16*)p_w2h, (__nv_bfloat16*)p_w2l, F1, HIDDEN);
    }

    const int MBLK = (NNODES + 127) / 128;   // 391

    // ---- layer 1 ----
    {
        dim3 grid(F1/128, MBLK);
        mma_gemm<128><<<grid, 256, SMEM1>>>((const __nv_bfloat16*)p_xhi, (const __nv_bfloat16*)p_xlo,
                                            (const __nv_bfloat16*)p_w1h, (const __nv_bfloat16*)p_w1l,
                                            (float*)p_h1, NNODES, F1, INF_);
    }
    attn_scores1<<<(NNODES*HEADS + 255)/256, 256>>>(att_src1, att_dst1);
    gather1<<<(NNODES*32 + 255)/256, 256>>>(b1);

    // ---- layer 2 ----
    {
        dim3 grid(HIDDEN/64, MBLK);
        mma_gemm<64><<<grid, 256, SMEM2>>>((const __nv_bfloat16*)p_o1h, (const __nv_bfloat16*)p_o1l,
                                           (const __nv_bfloat16*)p_w2h, (const __nv_bfloat16*)p_w2l,
                                           (float*)p_h2, NNODES, HIDDEN, F1);
    }
    attn_scores2<<<(NNODES + 255)/256, 256>>>(att_src2, att_dst2);
    gather2<<<(NNODES*32 + 255)/256, 256>>>(b2);

    // ---- MLP head ----
    mlp_kernel<<<(NNODES + 31)/32, 256>>>(mw1, mb1, mw2, mb2, out);
}